// round 4
// baseline (speedup 1.0000x reference)
#include <cuda_runtime.h>
#include <cuda_bf16.h>
#include <cstddef>

// ---------------------------------------------------------------------------
// Problem constants
// ---------------------------------------------------------------------------
#define B_SZ      4096
#define IN_DIM    512
#define LATENT    512
#define NHEAD     8
#define DHEAD     64
#define KVB_N     (NHEAD * (2 * DHEAD + 1))   // 1032
#define LN_EPS    1e-5f

// ---------------------------------------------------------------------------
// Scratch (allocation-free: __device__ globals)
// ---------------------------------------------------------------------------
__device__ float g_h  [B_SZ * LATENT];   // h (pre-LN, then LN'd in place)
__device__ float g_h2 [B_SZ * LATENT];   // merge-gate output
__device__ float g_kvb[B_SZ * KVB_N];    // activated kvb

// ---------------------------------------------------------------------------
// SGEMM: C[M,N] = A[M,K] @ Bmat[K,N] + bias  (A optionally concat of A0|A1)
// BM=128 BN=64 BK=16, 256 threads, 8x4 per-thread microtile
// MODE 0: bias only.  MODE 1: bias + kvb head activations (tanh / sigmoid)
// ---------------------------------------------------------------------------
#define BM 128
#define BN 64
#define BK 16
#define TM 8
#define TN 4

template <int MODE>
__global__ __launch_bounds__(256, 2)
void sgemm_kernel(const float* __restrict__ A0, const float* __restrict__ A1, int K0,
                  const float* __restrict__ Bmat, const float* __restrict__ bias,
                  float* __restrict__ C, int M, int N, int K)
{
    __shared__ float As[BK][BM];
    __shared__ float Bs[BK][BN];

    const int tid = threadIdx.x;
    const int tx  = tid & 15;   // N direction (16 * TN = 64)
    const int ty  = tid >> 4;   // M direction (16 * TM = 128)
    const int m0  = blockIdx.y * BM;
    const int n0  = blockIdx.x * BN;

    float acc[TM][TN] = {};

    for (int k0 = 0; k0 < K; k0 += BK) {
        // ---- load A tile (128x16 = 512 float4, 2 per thread), store transposed
        #pragma unroll
        for (int i = 0; i < 2; ++i) {
            int idx = tid + i * 256;
            int ar  = idx >> 2;
            int ac  = (idx & 3) * 4;
            int gk  = k0 + ac;
            float4 v;
            if (gk < K0) {
                v = *(const float4*)(A0 + (size_t)(m0 + ar) * K0 + gk);
            } else {
                v = *(const float4*)(A1 + (size_t)(m0 + ar) * (K - K0) + (gk - K0));
            }
            As[ac + 0][ar] = v.x;
            As[ac + 1][ar] = v.y;
            As[ac + 2][ar] = v.z;
            As[ac + 3][ar] = v.w;
        }
        // ---- load B tile (16x64 = 256 float4, 1 per thread)
        {
            int br = tid >> 4;
            int bc = (tid & 15) * 4;
            int gn = n0 + bc;
            float4 v = make_float4(0.f, 0.f, 0.f, 0.f);
            if (gn < N)
                v = *(const float4*)(Bmat + (size_t)(k0 + br) * N + gn);
            *(float4*)&Bs[br][bc] = v;
        }
        __syncthreads();

        #pragma unroll
        for (int kk = 0; kk < BK; ++kk) {
            // vectorized shared reads: A as 2x float4, B as 1x float4
            float4 a0 = *(const float4*)&As[kk][ty * TM + 0];
            float4 a1 = *(const float4*)&As[kk][ty * TM + 4];
            float4 b0 = *(const float4*)&Bs[kk][tx * TN];
            float a[TM] = {a0.x, a0.y, a0.z, a0.w, a1.x, a1.y, a1.z, a1.w};
            float bb[TN] = {b0.x, b0.y, b0.z, b0.w};
            #pragma unroll
            for (int i = 0; i < TM; ++i)
                #pragma unroll
                for (int j = 0; j < TN; ++j)
                    acc[i][j] = fmaf(a[i], bb[j], acc[i][j]);
        }
        __syncthreads();
    }

    // ---- epilogue
    #pragma unroll
    for (int i = 0; i < TM; ++i) {
        int m = m0 + ty * TM + i;
        #pragma unroll
        for (int j = 0; j < TN; ++j) {
            int n = n0 + tx * TN + j;
            if (n < N) {
                float c = acc[i][j] + bias[n];
                if (MODE == 1) {
                    int r = n % 129;            // position within head block
                    if (r >= 128)      c = 1.f / (1.f + __expf(-c));  // lr: sigmoid
                    else if (r >= 64)  c = tanhf(c);                  // vs: tanh
                }
                C[(size_t)m * N + n] = c;
            }
        }
    }
}

// ---------------------------------------------------------------------------
// In-place LayerNorm over rows of 512.  4096 blocks x 128 threads.
// ---------------------------------------------------------------------------
__global__ __launch_bounds__(128)
void ln_kernel(float* __restrict__ h, const float* __restrict__ g,
               const float* __restrict__ b)
{
    const int row = blockIdx.x;
    float* hp = h + (size_t)row * LATENT;
    const int tid = threadIdx.x;

    float4 v = ((const float4*)hp)[tid];
    float s  = v.x + v.y + v.z + v.w;
    float sq = v.x * v.x + v.y * v.y + v.z * v.z + v.w * v.w;

    __shared__ float rs[4], rq[4];
    #pragma unroll
    for (int o = 16; o; o >>= 1) {
        s  += __shfl_xor_sync(0xffffffffu, s,  o);
        sq += __shfl_xor_sync(0xffffffffu, sq, o);
    }
    if ((tid & 31) == 0) { rs[tid >> 5] = s; rq[tid >> 5] = sq; }
    __syncthreads();
    s  = rs[0] + rs[1] + rs[2] + rs[3];
    sq = rq[0] + rq[1] + rq[2] + rq[3];

    const float mu  = s * (1.f / LATENT);
    const float var = sq * (1.f / LATENT) - mu * mu;
    const float inv = rsqrtf(var + LN_EPS);

    float4 gg = ((const float4*)g)[tid];
    float4 bb = ((const float4*)b)[tid];
    v.x = (v.x - mu) * inv * gg.x + bb.x;
    v.y = (v.y - mu) * inv * gg.y + bb.y;
    v.z = (v.z - mu) * inv * gg.z + bb.z;
    v.w = (v.w - mu) * inv * gg.w + bb.w;
    ((float4*)hp)[tid] = v;
}

// ---------------------------------------------------------------------------
// Fused Oja update.  One CTA per (b,h): 64x64 W tile in registers.
//   ks_remove[e] = sum_d W[d,e] * vs[d]
//   ks_ = softmax(ks - ks_remove) * lr
//   out[d,e] = vs[d] * ks_[e] + W[d,e]
// 256 threads: e = tid&63 (column), q = tid>>6 (16-row slab); W coalesced.
// ---------------------------------------------------------------------------
__global__ __launch_bounds__(256)
void oja_kernel(const float* __restrict__ kvb, const float* __restrict__ W,
                float* __restrict__ out)
{
    const int bh = blockIdx.x;              // b * 8 + h
    const int b  = bh >> 3;
    const int h  = bh & 7;

    const float* kb = kvb + (size_t)b * KVB_N + h * 129;
    const float* Wp = W   + (size_t)bh * (DHEAD * DHEAD);
    float*       Op = out + (size_t)bh * (DHEAD * DHEAD);

    __shared__ float ks_s[64], vs_s[64], ksf[64];
    __shared__ float red4[4 * 64];
    __shared__ float wred[8];
    __shared__ float lr_s;

    const int tid = threadIdx.x;
    if (tid < 64)       { ks_s[tid] = kb[tid]; vs_s[tid] = kb[64 + tid]; }
    else if (tid == 64) { lr_s = kb[128]; }
    __syncthreads();

    const int e = tid & 63;
    const int q = tid >> 6;

    float w[16];
    float partial = 0.f;
    #pragma unroll
    for (int i = 0; i < 16; ++i) {
        int d = q * 16 + i;
        w[i] = Wp[d * 64 + e];                       // warp-coalesced 128B lines
        partial = fmaf(w[i], vs_s[d], partial);
    }
    red4[q * 64 + e] = partial;
    __syncthreads();

    // --- softmax over e (uniform control flow; tid>=64 carry neutral values)
    float v = -1e30f;
    if (tid < 64)
        v = ks_s[e] - (red4[e] + red4[64 + e] + red4[128 + e] + red4[192 + e]);

    float m = v;
    #pragma unroll
    for (int o = 16; o; o >>= 1) m = fmaxf(m, __shfl_xor_sync(0xffffffffu, m, o));
    if ((tid & 31) == 0) wred[tid >> 5] = m;
    __syncthreads();
    m = wred[0];
    #pragma unroll
    for (int i = 1; i < 8; ++i) m = fmaxf(m, wred[i]);
    __syncthreads();                                  // before reusing wred

    float ex = (tid < 64) ? __expf(v - m) : 0.f;
    float sm = ex;
    #pragma unroll
    for (int o = 16; o; o >>= 1) sm += __shfl_xor_sync(0xffffffffu, sm, o);
    if ((tid & 31) == 0) wred[tid >> 5] = sm;
    __syncthreads();
    sm = wred[0] + wred[1] + wred[2] + wred[3] + wred[4] + wred[5] + wred[6] + wred[7];

    if (tid < 64) ksf[e] = ex * lr_s / sm;
    __syncthreads();

    const float ke = ksf[e];
    #pragma unroll
    for (int i = 0; i < 16; ++i) {
        int d = q * 16 + i;
        Op[d * 64 + e] = fmaf(vs_s[d], ke, w[i]);     // W reused from registers
    }
}

// ---------------------------------------------------------------------------
// Launch
// ---------------------------------------------------------------------------
extern "C" void kernel_launch(void* const* d_in, const int* in_sizes, int n_in,
                              void* d_out, int out_size)
{
    const float* x     = (const float*)d_in[0];
    const float* z     = (const float*)d_in[1];
    const float* W     = (const float*)d_in[2];
    const float* ip_w  = (const float*)d_in[3];
    const float* ip_b  = (const float*)d_in[4];
    const float* ln_g  = (const float*)d_in[5];
    const float* ln_b  = (const float*)d_in[6];
    const float* mg_w  = (const float*)d_in[7];
    const float* mg_b  = (const float*)d_in[8];
    const float* kvb_w = (const float*)d_in[9];
    const float* kvb_b = (const float*)d_in[10];
    float* out = (float*)d_out;

    void *ph, *ph2, *pkvb;
    cudaGetSymbolAddress(&ph,   g_h);
    cudaGetSymbolAddress(&ph2,  g_h2);
    cudaGetSymbolAddress(&pkvb, g_kvb);
    float* h   = (float*)ph;
    float* h2  = (float*)ph2;
    float* kvb = (float*)pkvb;

    // 1) h = x @ ip_w + ip_b            (M=4096, N=512, K=512)
    {
        dim3 grid(LATENT / BN, B_SZ / BM);
        sgemm_kernel<0><<<grid, 256>>>(x, nullptr, IN_DIM, ip_w, ip_b,
                                       h, B_SZ, LATENT, IN_DIM);
    }
    // 2) LayerNorm in place
    ln_kernel<<<B_SZ, 128>>>(h, ln_g, ln_b);

    // 3) h2 = concat(h, z) @ mg_w + mg_b   (K=1024, split at 512)
    {
        dim3 grid(LATENT / BN, B_SZ / BM);
        sgemm_kernel<0><<<grid, 256>>>(h, z, LATENT, mg_w, mg_b,
                                       h2, B_SZ, LATENT, 2 * LATENT);
    }
    // 4) kvb = act(h2 @ kvb_w + kvb_b)     (N=1032, fused tanh/sigmoid)
    {
        dim3 grid((KVB_N + BN - 1) / BN, B_SZ / BM);
        sgemm_kernel<1><<<grid, 256>>>(h2, nullptr, LATENT, kvb_w, kvb_b,
                                       kvb, B_SZ, KVB_N, LATENT);
    }
    // 5) fused Oja update                  (32768 CTAs, DRAM-bound)
    oja_kernel<<<B_SZ * NHEAD, 256>>>(kvb, W, out);
}

// round 5
// speedup vs baseline: 1.4614x; 1.4614x over previous
#include <cuda_runtime.h>
#include <cuda_bf16.h>
#include <cstddef>

// ---------------------------------------------------------------------------
// Problem constants
// ---------------------------------------------------------------------------
#define B_SZ      4096
#define IN_DIM    512
#define LATENT    512
#define NHEAD     8
#define DHEAD     64
#define KVB_N     (NHEAD * (2 * DHEAD + 1))   // 1032
#define LN_EPS    1e-5f

// ---------------------------------------------------------------------------
// Scratch (allocation-free: __device__ globals)
// ---------------------------------------------------------------------------
__device__ float g_h  [B_SZ * LATENT];
__device__ float g_h2 [B_SZ * LATENT];
__device__ float g_kvb[B_SZ * KVB_N];

// ---------------------------------------------------------------------------
// TF32 tensor-core GEMM:  C[M,N] = A[M,K] @ B[K,N] + bias, A = concat(A0|A1)
// BM=128 BN=64 BK=32, 256 threads = 8 warps (4 in M x 2 in N),
// warp tile 32x32 = 2x4 m16n8k8 atoms. Double-buffered smem in a
// fragment-shuffled layout: conflict-free LDS.128/LDS.64 fragment loads.
// MODE 0: bias.  MODE 1: bias + kvb activations (tanh / sigmoid per head slot)
// ---------------------------------------------------------------------------
__device__ __forceinline__ unsigned f2tf32(float f) {
    unsigned u; asm("cvt.rna.tf32.f32 %0, %1;" : "=r"(u) : "f"(f)); return u;
}

__device__ __forceinline__ float kvb_act(float c, int n) {
    int r = n % 129;
    if (r >= 128) return 1.f / (1.f + __expf(-c));
    if (r >= 64)  return tanhf(c);
    return c;
}

template <int MODE>
__global__ __launch_bounds__(256, 2)
void tf32_gemm(const float* __restrict__ A0, const float* __restrict__ A1, int K0,
               const float* __restrict__ Bm, const float* __restrict__ bias,
               float* __restrict__ C, int N, int K)
{
    // A: per kstep(4) x 16-row-block(8): 32 lanes x 4 slots  -> 4096 words
    // B: per kstep(4) x  8-col-block(8): 32 lanes x 2 slots  -> 2048 words
    __shared__ unsigned As[2][4096];
    __shared__ unsigned Bs[2][2048];

    const int tid  = threadIdx.x;
    const int lane = tid & 31;
    const int wid  = tid >> 5;
    const int wm   = wid & 3;          // warp row   (32 rows each)
    const int wn   = wid >> 2;         // warp col   (32 cols each)
    const int m0   = blockIdx.y * 128;
    const int n0   = blockIdx.x * 64;
    const int K1   = K - K0;

    float acc[2][4][4] = {};
    float4 ra[2][2];                    // [unit][row m / m+8]
    float4 rb[2];

    const int NT = K >> 5;              // K / 32

    // ---------------- global load (register prefetch) ----------------
    auto ldgA = [&](int it) {
        int kb = it * 32;
        #pragma unroll
        for (int u = 0; u < 2; ++u) {
            int idx = u * 256 + tid;
            int c   = idx & 7;                 // k-chunk of 4 (ks=c>>1, kh=c&1)
            int r   = idx >> 3;                // row-pair id
            int g   = r & 7, am = r >> 3;
            int row = m0 + am * 16 + g;
            int gk  = kb + c * 4;
            if (gk < K0) {
                const float* s = A0 + (size_t)row * K0 + gk;
                ra[u][0] = *(const float4*)s;
                ra[u][1] = *(const float4*)(s + 8 * K0);
            } else {
                const float* s = A1 + (size_t)row * K1 + (gk - K0);
                ra[u][0] = *(const float4*)s;
                ra[u][1] = *(const float4*)(s + 8 * K1);
            }
        }
    };
    auto ldgB = [&](int it) {
        int kb = it * 32;
        #pragma unroll
        for (int u = 0; u < 2; ++u) {
            int idx = u * 256 + tid;
            int nc = idx & 15, k = idx >> 4;
            int n  = n0 + nc * 4;
            if (n < N) rb[u] = *(const float4*)(Bm + (size_t)(kb + k) * N + n);
            else       rb[u] = make_float4(0.f, 0.f, 0.f, 0.f);
        }
    };

    // ---------------- shuffled smem stores ----------------
    auto stsA = [&](int buf) {
        #pragma unroll
        for (int u = 0; u < 2; ++u) {
            int idx = u * 256 + tid;
            int c = idx & 7, r = idx >> 3;
            int ks = c >> 1, kh = c & 1, g = r & 7, am = r >> 3;
            const float* a0p = (const float*)&ra[u][0];
            const float* a1p = (const float*)&ra[u][1];
            unsigned rg = (unsigned)(ks * 8 + am) * 128;
            #pragma unroll
            for (int jj = 0; jj < 4; ++jj) {
                int j = (jj + ks) & 3;             // bank-conflict rotation
                unsigned off = rg + (g * 4 + j) * 4 + 2 * kh;
                *(uint2*)&As[buf][off] = make_uint2(f2tf32(a0p[j]), f2tf32(a1p[j]));
            }
        }
    };
    auto stsB = [&](int buf) {
        #pragma unroll
        for (int u = 0; u < 2; ++u) {
            int idx = u * 256 + tid;
            int nc = idx & 15, k = idx >> 4;
            int ks = k >> 3, t = k & 3, kh = (k >> 2) & 1;
            int an = nc >> 1;
            const float* bp = (const float*)&rb[u];
            unsigned rg = (unsigned)(ks * 8 + an) * 64;
            #pragma unroll
            for (int jj = 0; jj < 4; ++jj) {
                int j = (jj + nc) & 3;             // rotation
                int g = (nc & 1) * 4 + j;
                Bs[buf][rg + (g * 4 + t) * 2 + kh] = f2tf32(bp[j]);
            }
        }
    };

    // ---------------- mma compute over one smem stage ----------------
    auto compute = [&](int buf) {
        #pragma unroll
        for (int ks = 0; ks < 4; ++ks) {
            unsigned a[2][4], b[4][2];
            #pragma unroll
            for (int am = 0; am < 2; ++am) {
                uint4 v = *(const uint4*)&As[buf][(ks * 8 + wm * 2 + am) * 128 + lane * 4];
                a[am][0] = v.x; a[am][1] = v.y; a[am][2] = v.z; a[am][3] = v.w;
            }
            #pragma unroll
            for (int an = 0; an < 4; ++an) {
                uint2 v = *(const uint2*)&Bs[buf][(ks * 8 + wn * 4 + an) * 64 + lane * 2];
                b[an][0] = v.x; b[an][1] = v.y;
            }
            #pragma unroll
            for (int am = 0; am < 2; ++am)
                #pragma unroll
                for (int an = 0; an < 4; ++an)
                    asm volatile(
                        "mma.sync.aligned.m16n8k8.row.col.f32.tf32.tf32.f32 "
                        "{%0,%1,%2,%3}, {%4,%5,%6,%7}, {%8,%9}, {%0,%1,%2,%3};"
                        : "+f"(acc[am][an][0]), "+f"(acc[am][an][1]),
                          "+f"(acc[am][an][2]), "+f"(acc[am][an][3])
                        : "r"(a[am][0]), "r"(a[am][1]), "r"(a[am][2]), "r"(a[am][3]),
                          "r"(b[an][0]), "r"(b[an][1]));
        }
    };

    // ---------------- main loop (double-buffered) ----------------
    ldgA(0); ldgB(0);
    stsA(0); stsB(0);
    __syncthreads();
    for (int it = 0; it < NT; ++it) {
        int cur = it & 1;
        if (it + 1 < NT) { ldgA(it + 1); ldgB(it + 1); }
        compute(cur);
        if (it + 1 < NT) { stsA(cur ^ 1); stsB(cur ^ 1); __syncthreads(); }
    }

    // ---------------- epilogue ----------------
    const int g = lane >> 2, t = lane & 3;
    #pragma unroll
    for (int am = 0; am < 2; ++am) {
        int row = m0 + wm * 32 + am * 16 + g;
        #pragma unroll
        for (int an = 0; an < 4; ++an) {
            int nb = n0 + wn * 32 + an * 8;
            if (nb < N) {                          // N is a multiple of 8
                int n = nb + t * 2;
                float bx = bias[n], by = bias[n + 1];
                float c0 = acc[am][an][0] + bx;
                float c1 = acc[am][an][1] + by;
                float c2 = acc[am][an][2] + bx;
                float c3 = acc[am][an][3] + by;
                if (MODE == 1) {
                    c0 = kvb_act(c0, n);   c1 = kvb_act(c1, n + 1);
                    c2 = kvb_act(c2, n);   c3 = kvb_act(c3, n + 1);
                }
                *(float2*)&C[(size_t)row * N + n]       = make_float2(c0, c1);
                *(float2*)&C[(size_t)(row + 8) * N + n] = make_float2(c2, c3);
            }
        }
    }
}

// ---------------------------------------------------------------------------
// In-place LayerNorm over rows of 512.  4096 blocks x 128 threads.
// ---------------------------------------------------------------------------
__global__ __launch_bounds__(128)
void ln_kernel(float* __restrict__ h, const float* __restrict__ g,
               const float* __restrict__ b)
{
    const int row = blockIdx.x;
    float* hp = h + (size_t)row * LATENT;
    const int tid = threadIdx.x;

    float4 v = ((const float4*)hp)[tid];
    float s  = v.x + v.y + v.z + v.w;
    float sq = v.x * v.x + v.y * v.y + v.z * v.z + v.w * v.w;

    __shared__ float rs[4], rq[4];
    #pragma unroll
    for (int o = 16; o; o >>= 1) {
        s  += __shfl_xor_sync(0xffffffffu, s,  o);
        sq += __shfl_xor_sync(0xffffffffu, sq, o);
    }
    if ((tid & 31) == 0) { rs[tid >> 5] = s; rq[tid >> 5] = sq; }
    __syncthreads();
    s  = rs[0] + rs[1] + rs[2] + rs[3];
    sq = rq[0] + rq[1] + rq[2] + rq[3];

    const float mu  = s * (1.f / LATENT);
    const float var = sq * (1.f / LATENT) - mu * mu;
    const float inv = rsqrtf(var + LN_EPS);

    float4 gg = ((const float4*)g)[tid];
    float4 bb = ((const float4*)b)[tid];
    v.x = (v.x - mu) * inv * gg.x + bb.x;
    v.y = (v.y - mu) * inv * gg.y + bb.y;
    v.z = (v.z - mu) * inv * gg.z + bb.z;
    v.w = (v.w - mu) * inv * gg.w + bb.w;
    ((float4*)hp)[tid] = v;
}

// ---------------------------------------------------------------------------
// Fused Oja update.  One CTA per (b,h): 64x64 W tile in registers.
// ---------------------------------------------------------------------------
__global__ __launch_bounds__(256)
void oja_kernel(const float* __restrict__ kvb, const float* __restrict__ W,
                float* __restrict__ out)
{
    const int bh = blockIdx.x;
    const int b  = bh >> 3;
    const int h  = bh & 7;

    const float* kb = kvb + (size_t)b * KVB_N + h * 129;
    const float* Wp = W   + (size_t)bh * (DHEAD * DHEAD);
    float*       Op = out + (size_t)bh * (DHEAD * DHEAD);

    __shared__ float ks_s[64], vs_s[64], ksf[64];
    __shared__ float red4[4 * 64];
    __shared__ float wred[8];
    __shared__ float lr_s;

    const int tid = threadIdx.x;
    if (tid < 64)       { ks_s[tid] = kb[tid]; vs_s[tid] = kb[64 + tid]; }
    else if (tid == 64) { lr_s = kb[128]; }
    __syncthreads();

    const int e = tid & 63;
    const int q = tid >> 6;

    float w[16];
    float partial = 0.f;
    #pragma unroll
    for (int i = 0; i < 16; ++i) {
        int d = q * 16 + i;
        w[i] = Wp[d * 64 + e];
        partial = fmaf(w[i], vs_s[d], partial);
    }
    red4[q * 64 + e] = partial;
    __syncthreads();

    float v = -1e30f;
    if (tid < 64)
        v = ks_s[e] - (red4[e] + red4[64 + e] + red4[128 + e] + red4[192 + e]);

    float m = v;
    #pragma unroll
    for (int o = 16; o; o >>= 1) m = fmaxf(m, __shfl_xor_sync(0xffffffffu, m, o));
    if ((tid & 31) == 0) wred[tid >> 5] = m;
    __syncthreads();
    m = wred[0];
    #pragma unroll
    for (int i = 1; i < 8; ++i) m = fmaxf(m, wred[i]);
    __syncthreads();

    float ex = (tid < 64) ? __expf(v - m) : 0.f;
    float sm = ex;
    #pragma unroll
    for (int o = 16; o; o >>= 1) sm += __shfl_xor_sync(0xffffffffu, sm, o);
    if ((tid & 31) == 0) wred[tid >> 5] = sm;
    __syncthreads();
    sm = wred[0] + wred[1] + wred[2] + wred[3] + wred[4] + wred[5] + wred[6] + wred[7];

    if (tid < 64) ksf[e] = ex * lr_s / sm;
    __syncthreads();

    const float ke = ksf[e];
    #pragma unroll
    for (int i = 0; i < 16; ++i) {
        int d = q * 16 + i;
        Op[d * 64 + e] = fmaf(vs_s[d], ke, w[i]);
    }
}

// ---------------------------------------------------------------------------
// Launch
// ---------------------------------------------------------------------------
extern "C" void kernel_launch(void* const* d_in, const int* in_sizes, int n_in,
                              void* d_out, int out_size)
{
    const float* x     = (const float*)d_in[0];
    const float* z     = (const float*)d_in[1];
    const float* W     = (const float*)d_in[2];
    const float* ip_w  = (const float*)d_in[3];
    const float* ip_b  = (const float*)d_in[4];
    const float* ln_g  = (const float*)d_in[5];
    const float* ln_b  = (const float*)d_in[6];
    const float* mg_w  = (const float*)d_in[7];
    const float* mg_b  = (const float*)d_in[8];
    const float* kvb_w = (const float*)d_in[9];
    const float* kvb_b = (const float*)d_in[10];
    float* out = (float*)d_out;

    void *ph, *ph2, *pkvb;
    cudaGetSymbolAddress(&ph,   g_h);
    cudaGetSymbolAddress(&ph2,  g_h2);
    cudaGetSymbolAddress(&pkvb, g_kvb);
    float* h   = (float*)ph;
    float* h2  = (float*)ph2;
    float* kvb = (float*)pkvb;

    // 1) h = x @ ip_w + ip_b               (M=4096, N=512, K=512)
    tf32_gemm<0><<<dim3(LATENT / 64, B_SZ / 128), 256>>>(
        x, nullptr, IN_DIM, ip_w, ip_b, h, LATENT, IN_DIM);

    // 2) LayerNorm in place
    ln_kernel<<<B_SZ, 128>>>(h, ln_g, ln_b);

    // 3) h2 = concat(h, z) @ mg_w + mg_b   (K=1024, split at 512)
    tf32_gemm<0><<<dim3(LATENT / 64, B_SZ / 128), 256>>>(
        h, z, LATENT, mg_w, mg_b, h2, LATENT, 2 * LATENT);

    // 4) kvb = act(h2 @ kvb_w + kvb_b)     (N=1032)
    tf32_gemm<1><<<dim3((KVB_N + 63) / 64, B_SZ / 128), 256>>>(
        h2, nullptr, LATENT, kvb_w, kvb_b, kvb, KVB_N, LATENT);

    // 5) fused Oja update                  (32768 CTAs, DRAM-bound)
    oja_kernel<<<B_SZ * NHEAD, 256>>>(kvb, W, out);
}

// round 6
// speedup vs baseline: 1.8568x; 1.2706x over previous
#include <cuda_runtime.h>
#include <cuda_bf16.h>
#include <cstddef>

// ---------------------------------------------------------------------------
// Problem constants
// ---------------------------------------------------------------------------
#define B_SZ      4096
#define IN_DIM    512
#define LATENT    512
#define NHEAD     8
#define DHEAD     64
#define KVB_N     (NHEAD * (2 * DHEAD + 1))   // 1032
#define LN_EPS    1e-5f

// ---------------------------------------------------------------------------
// Scratch (allocation-free: __device__ globals)
// ---------------------------------------------------------------------------
__device__ float g_h  [B_SZ * LATENT];
__device__ float g_h2 [B_SZ * LATENT];
__device__ float g_kvb[B_SZ * KVB_N];

// ---------------------------------------------------------------------------
// TF32 tensor-core GEMM v2:
//   C[M,N] = A[M,K] @ B[K,N] + bias, A = concat(A0|A1) along K
// BM=128 BN=128 BK=16, 256 threads = 8 warps (2 in M x 4 in N),
// warp tile 64x32 = 4x4 m16n8k8 atoms.
// cp.async double-buffered global->shared (raw fp32 bits; tf32 HW truncates).
// Padded smem layouts give conflict-free scalar fragment LDS:
//   A row stride 20 words : banks (20*g + t) % 32 cover all 32
//   B row stride 136 words: banks (136*t + g) % 32 cover all 32
// MODE 0: bias.  MODE 1: bias + kvb activations (tanh / sigmoid per head slot)
// ---------------------------------------------------------------------------
#define BM 128
#define BN 128
#define BK 16
#define ASTRIDE 20    // 16 + 4 pad (80B rows, 16B aligned)
#define BSTRIDE 136   // 128 + 8 pad (544B rows, 16B aligned)

__device__ __forceinline__ float kvb_act(float c, int n) {
    int r = n % 129;
    if (r >= 128) return 1.f / (1.f + __expf(-c));
    if (r >= 64)  return tanhf(c);
    return c;
}

template <int MODE>
__global__ __launch_bounds__(256, 2)
void tf32_gemm(const float* __restrict__ A0, const float* __restrict__ A1, int K0,
               const float* __restrict__ Bm, const float* __restrict__ bias,
               float* __restrict__ C, int N, int K)
{
    __shared__ float As[2][BM * ASTRIDE];   // 2 x 10240 B
    __shared__ float Bs[2][BK * BSTRIDE];   // 2 x  8704 B

    const int tid  = threadIdx.x;
    const int lane = tid & 31;
    const int wid  = tid >> 5;
    const int wm   = wid & 1;            // warp row (64 rows each)
    const int wn   = wid >> 1;           // warp col (32 cols each)
    const int m0   = blockIdx.y * BM;
    const int n0   = blockIdx.x * BN;
    const int K1   = K - K0;
    const int g    = lane >> 2;          // 0..7
    const int t    = lane & 3;           // 0..3

    float acc[4][4][4] = {};

    // ---------------- async tile loads ----------------
    auto load_tiles = [&](int it, int buf) {
        const int kb = it * BK;
        // A: 128 rows x 4 chunks of 16B
        #pragma unroll
        for (int u = 0; u < 2; ++u) {
            int idx = u * 256 + tid;
            int row = idx >> 2;
            int kc  = (idx & 3) * 4;
            const float* src;
            if (kb < K0) src = A0 + (size_t)(m0 + row) * K0 + (kb + kc);
            else         src = A1 + (size_t)(m0 + row) * K1 + (kb - K0 + kc);
            unsigned dst = (unsigned)__cvta_generic_to_shared(
                               &As[buf][row * ASTRIDE + kc]);
            asm volatile("cp.async.cg.shared.global [%0], [%1], 16;"
                         :: "r"(dst), "l"(src));
        }
        // B: 16 k-rows x 32 chunks of 16B
        #pragma unroll
        for (int u = 0; u < 2; ++u) {
            int idx = u * 256 + tid;
            int k   = idx >> 5;
            int nc  = (idx & 31) * 4;
            unsigned dst = (unsigned)__cvta_generic_to_shared(
                               &Bs[buf][k * BSTRIDE + nc]);
            if (MODE == 1) {
                int n = n0 + nc;
                int sz = (n < N) ? 16 : 0;                 // zfill OOB cols
                const float* src = Bm + (size_t)(kb + k) * N + (sz ? n : 0);
                asm volatile("cp.async.cg.shared.global [%0], [%1], 16, %2;"
                             :: "r"(dst), "l"(src), "r"(sz));
            } else {
                const float* src = Bm + (size_t)(kb + k) * N + (n0 + nc);
                asm volatile("cp.async.cg.shared.global [%0], [%1], 16;"
                             :: "r"(dst), "l"(src));
            }
        }
        asm volatile("cp.async.commit_group;");
    };

    // ---------------- compute one BK=16 stage ----------------
    auto compute = [&](int buf) {
        #pragma unroll
        for (int ks = 0; ks < 2; ++ks) {
            unsigned a[4][4], b[4][2];
            #pragma unroll
            for (int ma = 0; ma < 4; ++ma) {
                const float* p = &As[buf][(wm * 64 + ma * 16 + g) * ASTRIDE + ks * 8 + t];
                a[ma][0] = __float_as_uint(p[0]);
                a[ma][1] = __float_as_uint(p[8 * ASTRIDE]);
                a[ma][2] = __float_as_uint(p[4]);
                a[ma][3] = __float_as_uint(p[8 * ASTRIDE + 4]);
            }
            #pragma unroll
            for (int na = 0; na < 4; ++na) {
                const float* p = &Bs[buf][(ks * 8 + t) * BSTRIDE + wn * 32 + na * 8 + g];
                b[na][0] = __float_as_uint(p[0]);
                b[na][1] = __float_as_uint(p[4 * BSTRIDE]);
            }
            #pragma unroll
            for (int ma = 0; ma < 4; ++ma)
                #pragma unroll
                for (int na = 0; na < 4; ++na)
                    asm volatile(
                        "mma.sync.aligned.m16n8k8.row.col.f32.tf32.tf32.f32 "
                        "{%0,%1,%2,%3}, {%4,%5,%6,%7}, {%8,%9}, {%0,%1,%2,%3};"
                        : "+f"(acc[ma][na][0]), "+f"(acc[ma][na][1]),
                          "+f"(acc[ma][na][2]), "+f"(acc[ma][na][3])
                        : "r"(a[ma][0]), "r"(a[ma][1]), "r"(a[ma][2]), "r"(a[ma][3]),
                          "r"(b[na][0]), "r"(b[na][1]));
        }
    };

    // ---------------- main loop ----------------
    const int NT = K >> 4;
    load_tiles(0, 0);
    for (int it = 0; it < NT; ++it) {
        const int buf = it & 1;
        if (it + 1 < NT) {
            load_tiles(it + 1, buf ^ 1);
            asm volatile("cp.async.wait_group 1;");
        } else {
            asm volatile("cp.async.wait_group 0;");
        }
        __syncthreads();
        compute(buf);
        __syncthreads();
    }

    // ---------------- epilogue ----------------
    #pragma unroll
    for (int ma = 0; ma < 4; ++ma) {
        int row = m0 + wm * 64 + ma * 16 + g;
        #pragma unroll
        for (int na = 0; na < 4; ++na) {
            int nb = n0 + wn * 32 + na * 8;
            if (MODE == 0 || nb < N) {           // N multiple of 8
                int n = nb + t * 2;
                float bx = bias[n], by = bias[n + 1];
                float c0 = acc[ma][na][0] + bx;
                float c1 = acc[ma][na][1] + by;
                float c2 = acc[ma][na][2] + bx;
                float c3 = acc[ma][na][3] + by;
                if (MODE == 1) {
                    c0 = kvb_act(c0, n);   c1 = kvb_act(c1, n + 1);
                    c2 = kvb_act(c2, n);   c3 = kvb_act(c3, n + 1);
                }
                *(float2*)&C[(size_t)row * N + n]       = make_float2(c0, c1);
                *(float2*)&C[(size_t)(row + 8) * N + n] = make_float2(c2, c3);
            }
        }
    }
}

// ---------------------------------------------------------------------------
// In-place LayerNorm over rows of 512.  4096 blocks x 128 threads.
// ---------------------------------------------------------------------------
__global__ __launch_bounds__(128)
void ln_kernel(float* __restrict__ h, const float* __restrict__ g,
               const float* __restrict__ b)
{
    const int row = blockIdx.x;
    float* hp = h + (size_t)row * LATENT;
    const int tid = threadIdx.x;

    float4 v = ((const float4*)hp)[tid];
    float s  = v.x + v.y + v.z + v.w;
    float sq = v.x * v.x + v.y * v.y + v.z * v.z + v.w * v.w;

    __shared__ float rs[4], rq[4];
    #pragma unroll
    for (int o = 16; o; o >>= 1) {
        s  += __shfl_xor_sync(0xffffffffu, s,  o);
        sq += __shfl_xor_sync(0xffffffffu, sq, o);
    }
    if ((tid & 31) == 0) { rs[tid >> 5] = s; rq[tid >> 5] = sq; }
    __syncthreads();
    s  = rs[0] + rs[1] + rs[2] + rs[3];
    sq = rq[0] + rq[1] + rq[2] + rq[3];

    const float mu  = s * (1.f / LATENT);
    const float var = sq * (1.f / LATENT) - mu * mu;
    const float inv = rsqrtf(var + LN_EPS);

    float4 gg = ((const float4*)g)[tid];
    float4 bb = ((const float4*)b)[tid];
    v.x = (v.x - mu) * inv * gg.x + bb.x;
    v.y = (v.y - mu) * inv * gg.y + bb.y;
    v.z = (v.z - mu) * inv * gg.z + bb.z;
    v.w = (v.w - mu) * inv * gg.w + bb.w;
    ((float4*)hp)[tid] = v;
}

// ---------------------------------------------------------------------------
// Fused Oja update.  One CTA per (b,h): 64x64 W tile in registers.
// ---------------------------------------------------------------------------
__global__ __launch_bounds__(256)
void oja_kernel(const float* __restrict__ kvb, const float* __restrict__ W,
                float* __restrict__ out)
{
    const int bh = blockIdx.x;
    const int b  = bh >> 3;
    const int h  = bh & 7;

    const float* kb = kvb + (size_t)b * KVB_N + h * 129;
    const float* Wp = W   + (size_t)bh * (DHEAD * DHEAD);
    float*       Op = out + (size_t)bh * (DHEAD * DHEAD);

    __shared__ float ks_s[64], vs_s[64], ksf[64];
    __shared__ float red4[4 * 64];
    __shared__ float wred[8];
    __shared__ float lr_s;

    const int tid = threadIdx.x;
    if (tid < 64)       { ks_s[tid] = kb[tid]; vs_s[tid] = kb[64 + tid]; }
    else if (tid == 64) { lr_s = kb[128]; }
    __syncthreads();

    const int e = tid & 63;
    const int q = tid >> 6;

    float w[16];
    float partial = 0.f;
    #pragma unroll
    for (int i = 0; i < 16; ++i) {
        int d = q * 16 + i;
        w[i] = Wp[d * 64 + e];
        partial = fmaf(w[i], vs_s[d], partial);
    }
    red4[q * 64 + e] = partial;
    __syncthreads();

    float v = -1e30f;
    if (tid < 64)
        v = ks_s[e] - (red4[e] + red4[64 + e] + red4[128 + e] + red4[192 + e]);

    float m = v;
    #pragma unroll
    for (int o = 16; o; o >>= 1) m = fmaxf(m, __shfl_xor_sync(0xffffffffu, m, o));
    if ((tid & 31) == 0) wred[tid >> 5] = m;
    __syncthreads();
    m = wred[0];
    #pragma unroll
    for (int i = 1; i < 8; ++i) m = fmaxf(m, wred[i]);
    __syncthreads();

    float ex = (tid < 64) ? __expf(v - m) : 0.f;
    float sm = ex;
    #pragma unroll
    for (int o = 16; o; o >>= 1) sm += __shfl_xor_sync(0xffffffffu, sm, o);
    if ((tid & 31) == 0) wred[tid >> 5] = sm;
    __syncthreads();
    sm = wred[0] + wred[1] + wred[2] + wred[3] + wred[4] + wred[5] + wred[6] + wred[7];

    if (tid < 64) ksf[e] = ex * lr_s / sm;
    __syncthreads();

    const float ke = ksf[e];
    #pragma unroll
    for (int i = 0; i < 16; ++i) {
        int d = q * 16 + i;
        Op[d * 64 + e] = fmaf(vs_s[d], ke, w[i]);
    }
}

// ---------------------------------------------------------------------------
// Launch
// ---------------------------------------------------------------------------
extern "C" void kernel_launch(void* const* d_in, const int* in_sizes, int n_in,
                              void* d_out, int out_size)
{
    const float* x     = (const float*)d_in[0];
    const float* z     = (const float*)d_in[1];
    const float* W     = (const float*)d_in[2];
    const float* ip_w  = (const float*)d_in[3];
    const float* ip_b  = (const float*)d_in[4];
    const float* ln_g  = (const float*)d_in[5];
    const float* ln_b  = (const float*)d_in[6];
    const float* mg_w  = (const float*)d_in[7];
    const float* mg_b  = (const float*)d_in[8];
    const float* kvb_w = (const float*)d_in[9];
    const float* kvb_b = (const float*)d_in[10];
    float* out = (float*)d_out;

    void *ph, *ph2, *pkvb;
    cudaGetSymbolAddress(&ph,   g_h);
    cudaGetSymbolAddress(&ph2,  g_h2);
    cudaGetSymbolAddress(&pkvb, g_kvb);
    float* h   = (float*)ph;
    float* h2  = (float*)ph2;
    float* kvb = (float*)pkvb;

    // 1) h = x @ ip_w + ip_b               (M=4096, N=512, K=512)
    tf32_gemm<0><<<dim3(LATENT / BN, B_SZ / BM), 256>>>(
        x, nullptr, IN_DIM, ip_w, ip_b, h, LATENT, IN_DIM);

    // 2) LayerNorm in place
    ln_kernel<<<B_SZ, 128>>>(h, ln_g, ln_b);

    // 3) h2 = concat(h, z) @ mg_w + mg_b   (K=1024, split at 512)
    tf32_gemm<0><<<dim3(LATENT / BN, B_SZ / BM), 256>>>(
        h, z, LATENT, mg_w, mg_b, h2, LATENT, 2 * LATENT);

    // 4) kvb = act(h2 @ kvb_w + kvb_b)     (N=1032)
    tf32_gemm<1><<<dim3((KVB_N + BN - 1) / BN, B_SZ / BM), 256>>>(
        h2, nullptr, LATENT, kvb_w, kvb_b, kvb, KVB_N, LATENT);

    // 5) fused Oja update                  (32768 CTAs, DRAM-bound)
    oja_kernel<<<B_SZ * NHEAD, 256>>>(kvb, W, out);
}